// round 3
// baseline (speedup 1.0000x reference)
#include <cuda_runtime.h>
#include <math.h>

#define NMAPS 32
#define CDIM 256
#define HW 4096          // 64*64
#define NCELLS 256       // 16*16 cells per map
#define THRESH 0.65f

// ---------------- device scratch (no allocations allowed) ----------------
__device__ float g_sim[NMAPS * HW];          // 32 x 64 x 64 similarity maps
__device__ float g_cell_score[NMAPS * NCELLS];
__device__ int   g_cell_idx[NMAPS * NCELLS]; // ly*64+lx within cell
__device__ float g_cmin_val[NMAPS * NCELLS];
__device__ int   g_cmin_idx[NMAPS * NCELLS]; // gy*1024+gx flat index

// ---------------------------------------------------------------------------
// K1: normalize ref rows + per-pixel feature norm + 32x4096x256 dot products.
// grid = 128 blocks, 256 threads. Each block: 32 pixels x 8 ref-groups(4 refs).
// ---------------------------------------------------------------------------
__global__ void k_sim(const float* __restrict__ feat, const float* __restrict__ ref) {
    __shared__ float sref[32][257];   // padded: row stride 257 -> conflict-free col sweeps
    __shared__ float sinv[32];
    int tid = threadIdx.x;

    for (int i = tid; i < 32 * 256; i += 256)
        sref[i >> 8][i & 255] = ref[i];
    __syncthreads();
    if (tid < 32) {
        float ss = 0.f;
        #pragma unroll 8
        for (int c = 0; c < 256; c++) { float v = sref[tid][c]; ss += v * v; }
        sinv[tid] = 1.0f / (sqrtf(ss) + 1e-12f);
    }
    __syncthreads();
    for (int i = tid; i < 32 * 256; i += 256)
        sref[i >> 8][i & 255] *= sinv[i >> 8];
    __syncthreads();

    int pix = blockIdx.x * 32 + (tid & 31);
    int rbase = (tid >> 5) * 4;   // warp-uniform -> smem broadcasts

    float a0 = 0.f, a1 = 0.f, a2 = 0.f, a3 = 0.f, ss = 0.f;
    const float* fp = feat + pix;
    #pragma unroll 4
    for (int c = 0; c < 256; c++) {
        float v = fp[c * HW];     // coalesced 128B per warp
        ss += v * v;
        a0 += sref[rbase + 0][c] * v;
        a1 += sref[rbase + 1][c] * v;
        a2 += sref[rbase + 2][c] * v;
        a3 += sref[rbase + 3][c] * v;
    }
    float inv = 1.0f / (sqrtf(ss) + 1e-12f);
    g_sim[(rbase + 0) * HW + pix] = a0 * inv;
    g_sim[(rbase + 1) * HW + pix] = a1 * inv;
    g_sim[(rbase + 2) * HW + pix] = a2 * inv;
    g_sim[(rbase + 3) * HW + pix] = a3 * inv;
}

// ---------------------------------------------------------------------------
// K2: per (map, cell): evaluate the 64x64 bilinear-upsampled cell from its 6x6
// source patch; record cell argmax (first-occurrence ties) and cell argmin
// (lowest flat-index ties). grid = (256 cells, 32 maps), 64 threads (one per oy).
// jax.image.resize bilinear == half-pixel centers + exact edge replication.
// ---------------------------------------------------------------------------
__global__ void k_cells() {
    int cell = blockIdx.x;
    int m = blockIdx.y;
    int cy = cell >> 4, cx = cell & 15;
    int tid = threadIdx.x;

    __shared__ float patch[6][8];
    if (tid < 36) {
        int i = tid / 6, j = tid - i * 6;
        int sr = min(max(4 * cy - 1 + i, 0), 63);
        int sc = min(max(4 * cx - 1 + j, 0), 63);
        patch[i][j] = g_sim[m * HW + sr * 64 + sc];
    }
    __syncthreads();

    int oy = tid;
    int gy = cy * 64 + oy;
    float fy = ((float)gy - 7.5f) * 0.0625f;      // exact in fp32
    int jy = (int)floorf(fy);
    jy = min(max(jy, 0), 62);
    float ty = fminf(fmaxf(fy - (float)jy, 0.f), 1.f);
    float wy0 = 1.0f - ty;                        // exact
    int li = jy - (4 * cy - 1);

    float bestv = -1e30f; int bestidx = 0;
    float minv = 1e30f;  int minidx = 0;
    #pragma unroll 8
    for (int ox = 0; ox < 64; ox++) {
        int gx = cx * 64 + ox;
        float fx = ((float)gx - 7.5f) * 0.0625f;
        int jx = (int)floorf(fx);
        jx = min(max(jx, 0), 62);
        float tx = fminf(fmaxf(fx - (float)jx, 0.f), 1.f);
        int lj = jx - (4 * cx - 1);
        // y-interpolate first (matches jax's separable contraction), then x
        float v0 = wy0 * patch[li][lj]     + ty * patch[li + 1][lj];
        float v1 = wy0 * patch[li][lj + 1] + ty * patch[li + 1][lj + 1];
        float v  = (1.0f - tx) * v0 + tx * v1;
        if (v > bestv) { bestv = v; bestidx = oy * 64 + ox; }   // first occurrence kept
        if (v < minv)  { minv = v;  minidx = gy * 1024 + gx; }  // first occurrence kept
    }

    __shared__ float smax[64]; __shared__ int simax[64];
    __shared__ float smin[64]; __shared__ int simin[64];
    smax[tid] = bestv; simax[tid] = bestidx;
    smin[tid] = minv;  simin[tid] = minidx;
    __syncthreads();
    if (tid == 0) {
        float bv = smax[0]; int bi = simax[0];
        float mv = smin[0]; int mi = simin[0];
        // oy ascending == intra-cell / flat index ascending -> strict compares
        // preserve first-occurrence semantics
        for (int t = 1; t < 64; t++) {
            if (smax[t] > bv) { bv = smax[t]; bi = simax[t]; }
            if (smin[t] < mv) { mv = smin[t]; mi = simin[t]; }
        }
        g_cell_score[m * NCELLS + cell] = bv;
        g_cell_idx[m * NCELLS + cell]   = bi;
        g_cmin_val[m * NCELLS + cell]   = mv;
        g_cmin_idx[m * NCELLS + cell]   = mi;
    }
}

// ---------------------------------------------------------------------------
// K3: per map: threshold, stable descending sort by score (rank counting ->
// unique ranks, collision-free scatter), plus global-min bg point.
// grid = 32 maps, 256 threads (one per cell).
// Output layout: points [32,256,3] at offset 0, bg [32,1,2] at offset 24576.
// ---------------------------------------------------------------------------
__global__ void k_sort(float* __restrict__ out) {
    int m = blockIdx.x;
    int tid = threadIdx.x;

    float score = g_cell_score[m * NCELLS + tid];
    int idx = g_cell_idx[m * NCELLS + tid];
    bool valid = score > THRESH;
    float key = valid ? score : -1.0f;

    __shared__ float skey[256];
    skey[tid] = key;
    __syncthreads();

    int rank = 0;
    for (int j = 0; j < 256; j++) {
        float kj = skey[j];
        if (kj > key || (kj == key && j < tid)) rank++;   // stable descending
    }

    int cy = tid >> 4, cx = tid & 15;
    int ly = idx >> 6, lx = idx & 63;
    float x = valid ? (float)(cx * 64 + lx) : -1.0f;
    float y = valid ? (float)(cy * 64 + ly) : -1.0f;
    float s = valid ? score : -1.0f;
    float* po = out + m * (NCELLS * 3) + rank * 3;
    po[0] = x; po[1] = y; po[2] = s;

    // bg: global min over the upsampled map; ties -> lowest flat index
    __shared__ float sv[256]; __shared__ int si[256];
    sv[tid] = g_cmin_val[m * NCELLS + tid];
    si[tid] = g_cmin_idx[m * NCELLS + tid];
    __syncthreads();
    if (tid == 0) {
        float mv = sv[0]; int mi = si[0];
        for (int t = 1; t < 256; t++) {
            if (sv[t] < mv || (sv[t] == mv && si[t] < mi)) { mv = sv[t]; mi = si[t]; }
        }
        float* pb = out + NMAPS * NCELLS * 3 + m * 2;
        pb[0] = (float)(mi & 1023);   // x = col
        pb[1] = (float)(mi >> 10);    // y = row
    }
}

// ---------------------------------------------------------------------------
extern "C" void kernel_launch(void* const* d_in, const int* in_sizes, int n_in,
                              void* d_out, int out_size) {
    const float* feat = (const float*)d_in[0];  // [1,256,64,64]
    const float* ref  = (const float*)d_in[1];  // [32,1,256]
    if (n_in >= 2 && in_sizes[0] == NMAPS * CDIM) {  // defensive: order by size
        ref  = (const float*)d_in[0];
        feat = (const float*)d_in[1];
    }
    (void)out_size;

    k_sim<<<128, 256>>>(feat, ref);
    dim3 g2(NCELLS, NMAPS);
    k_cells<<<g2, 64>>>();
    k_sort<<<NMAPS, 256>>>((float*)d_out);
}

// round 4
// speedup vs baseline: 1.5602x; 1.5602x over previous
#include <cuda_runtime.h>
#include <math.h>

#define NMAPS 32
#define CDIM 256
#define HW 4096          // 64*64
#define NCELLS 256       // 16*16 cells per map
#define NCHUNK 4         // split-K chunks (64 channels each)
#define THRESH 0.65f

// ---------------- device scratch (no allocations allowed) ----------------
__device__ float g_part[NCHUNK * NMAPS * HW];   // partial dots (raw ref, normalized feat pending)
__device__ float g_ssp[NCHUNK * HW];            // partial per-pixel sum-of-squares
__device__ float g_sim[NMAPS * HW];             // 32 x 64 x 64 scaled sim = dot * pinv  (missing rinv factor)
__device__ float g_cell_score[NMAPS * NCELLS];
__device__ int   g_cell_idx[NMAPS * NCELLS];    // ly*64+lx within cell
__device__ float g_cmin_val[NMAPS * NCELLS];
__device__ int   g_cmin_idx[NMAPS * NCELLS];    // gy*1024+gx flat index

// ---------------------------------------------------------------------------
// K1: split-K partial GEMM. grid = (128 pixel-tiles, 4 channel-chunks), 256 thr.
// Thread = (pixel 0..31, ref-group 0..7 of 4 refs). 64 channels per block.
// ref tile stored transposed so the 4 ref weights come from ONE broadcast LDS.128.
// ---------------------------------------------------------------------------
__global__ void k_gemm(const float* __restrict__ feat, const float* __restrict__ ref) {
    __shared__ float sref_t[64][32];   // [channel][ref], rows 128B -> float4 aligned
    int tid = threadIdx.x;
    int chunk = blockIdx.y;

    for (int i = tid; i < 64 * 32; i += 256) {
        int c = i >> 5, r = i & 31;
        sref_t[c][r] = ref[r * CDIM + chunk * 64 + c];
    }
    __syncthreads();

    int pix = blockIdx.x * 32 + (tid & 31);
    int rg  = tid >> 5;                 // warp-uniform
    const float* fp = feat + chunk * 64 * HW + pix;

    float a0 = 0.f, a1 = 0.f, a2 = 0.f, a3 = 0.f, ss = 0.f;
    #pragma unroll 8
    for (int c = 0; c < 64; c++) {
        float v = fp[c * HW];                                   // coalesced 128B/warp
        float4 r4 = *reinterpret_cast<const float4*>(&sref_t[c][rg * 4]); // broadcast
        ss += v * v;
        a0 = fmaf(r4.x, v, a0);
        a1 = fmaf(r4.y, v, a1);
        a2 = fmaf(r4.z, v, a2);
        a3 = fmaf(r4.w, v, a3);
    }
    float* po = g_part + (chunk * NMAPS + rg * 4) * HW + pix;
    po[0] = a0; po[HW] = a1; po[2 * HW] = a2; po[3 * HW] = a3;
    if (rg == 0) g_ssp[chunk * HW + pix] = ss;
}

// ---------------------------------------------------------------------------
// K1b: combine partials + feature-norm. grid = (16 pixel-tiles, 32 refs), 256 thr.
// ---------------------------------------------------------------------------
__global__ void k_combine() {
    int pix = blockIdx.x * 256 + threadIdx.x;
    int r = blockIdx.y;
    float ss = g_ssp[pix] + g_ssp[HW + pix] + g_ssp[2 * HW + pix] + g_ssp[3 * HW + pix];
    float pinv = 1.0f / (sqrtf(ss) + 1e-12f);
    float d = g_part[r * HW + pix]
            + g_part[(NMAPS + r) * HW + pix]
            + g_part[(2 * NMAPS + r) * HW + pix]
            + g_part[(3 * NMAPS + r) * HW + pix];
    g_sim[r * HW + pix] = d * pinv;
}

// ---------------------------------------------------------------------------
// K2: per (map, cell): separable bilinear eval of the 64x64 upsampled cell.
// Thread = ox (64 threads). X-interp once into sH[6][64] (conflict-free);
// per-oy weights/row-index precomputed in smem tables. Tracks cell argmax
// (first-occurrence row-major ties) and global-flat argmin.
// ---------------------------------------------------------------------------
__global__ void k_cells() {
    int cell = blockIdx.x;
    int m = blockIdx.y;
    int cy = cell >> 4, cx = cell & 15;
    int tid = threadIdx.x;   // ox, and oy for table setup

    __shared__ float patch[6][8];
    __shared__ float sH[6][64];
    __shared__ float2 sw[64];
    __shared__ int sli[64];
    __shared__ float rmaxv[2]; __shared__ int rmaxi[2];
    __shared__ float rminv[2]; __shared__ int rmini[2];

    if (tid < 36) {
        int i = tid / 6, j = tid - i * 6;
        int sr = min(max(4 * cy - 1 + i, 0), 63);
        int sc = min(max(4 * cx - 1 + j, 0), 63);
        patch[i][j] = g_sim[m * HW + sr * 64 + sc];
    }
    // per-oy table (oy = tid)
    {
        float fy = ((float)(cy * 64 + tid) - 7.5f) * 0.0625f;   // exact
        int jy = (int)floorf(fy);
        jy = min(max(jy, 0), 62);
        float ty = fminf(fmaxf(fy - (float)jy, 0.f), 1.f);
        sw[tid] = make_float2(1.0f - ty, ty);
        sli[tid] = jy - (4 * cy - 1);
    }
    __syncthreads();

    // x-interp column for this thread's ox
    {
        float fx = ((float)(cx * 64 + tid) - 7.5f) * 0.0625f;
        int jx = (int)floorf(fx);
        jx = min(max(jx, 0), 62);
        float tx = fminf(fmaxf(fx - (float)jx, 0.f), 1.f);
        int lj = jx - (4 * cx - 1);
        float wx0 = 1.0f - tx;
        #pragma unroll
        for (int i = 0; i < 6; i++)
            sH[i][tid] = wx0 * patch[i][lj] + tx * patch[i][lj + 1];
    }
    __syncthreads();

    float bestv = -1e30f; int bestoy = 0;
    float minv  =  1e30f; int minoy  = 0;
    #pragma unroll 8
    for (int oy = 0; oy < 64; oy++) {
        float2 w = sw[oy];                 // broadcast LDS.64
        int li = sli[oy];                  // broadcast
        float v = w.x * sH[li][tid] + w.y * sH[li + 1][tid];  // conflict-free
        if (v > bestv) { bestv = v; bestoy = oy; }  // smallest oy kept on ties
        if (v < minv)  { minv  = v; minoy  = oy; }
    }

    int bidx = bestoy * 64 + tid;                              // cell-local row-major
    int midx = ((cy * 64 + minoy) << 10) + cx * 64 + tid;      // global flat
    #pragma unroll
    for (int off = 16; off; off >>= 1) {
        float ov = __shfl_down_sync(0xFFFFFFFFu, bestv, off);
        int   oi = __shfl_down_sync(0xFFFFFFFFu, bidx, off);
        if (ov > bestv || (ov == bestv && oi < bidx)) { bestv = ov; bidx = oi; }
        float mv = __shfl_down_sync(0xFFFFFFFFu, minv, off);
        int   mi = __shfl_down_sync(0xFFFFFFFFu, midx, off);
        if (mv < minv || (mv == minv && mi < midx)) { minv = mv; midx = mi; }
    }
    int w = tid >> 5;
    if ((tid & 31) == 0) { rmaxv[w] = bestv; rmaxi[w] = bidx; rminv[w] = minv; rmini[w] = midx; }
    __syncthreads();
    if (tid == 0) {
        float bv = rmaxv[0]; int bi = rmaxi[0];
        if (rmaxv[1] > bv || (rmaxv[1] == bv && rmaxi[1] < bi)) { bv = rmaxv[1]; bi = rmaxi[1]; }
        float mv = rminv[0]; int mi = rmini[0];
        if (rminv[1] < mv || (rminv[1] == mv && rmini[1] < mi)) { mv = rminv[1]; mi = rmini[1]; }
        g_cell_score[m * NCELLS + cell] = bv;
        g_cell_idx[m * NCELLS + cell]   = bi;
        g_cmin_val[m * NCELLS + cell]   = mv;
        g_cmin_idx[m * NCELLS + cell]   = mi;
    }
}

// ---------------------------------------------------------------------------
// K3: per map: apply deferred ref-norm scale, threshold, stable descending
// rank sort (unique ranks -> collision-free scatter), and bg (global min).
// grid = 32 maps, 256 threads. Output: points [32,256,3] then bg [32,1,2].
// ---------------------------------------------------------------------------
__global__ void k_sort(float* __restrict__ out, const float* __restrict__ ref) {
    int m = blockIdx.x;
    int tid = threadIdx.x;

    // ref-norm reciprocal for this map
    __shared__ float red[8];
    __shared__ float s_rinv;
    {
        float v = ref[m * CDIM + tid];
        float p = v * v;
        #pragma unroll
        for (int off = 16; off; off >>= 1) p += __shfl_down_sync(0xFFFFFFFFu, p, off);
        if ((tid & 31) == 0) red[tid >> 5] = p;
    }
    __syncthreads();
    if (tid == 0) {
        float s = 0.f;
        #pragma unroll
        for (int i = 0; i < 8; i++) s += red[i];
        s_rinv = 1.0f / (sqrtf(s) + 1e-12f);
    }
    __syncthreads();
    float rinv = s_rinv;

    float score = g_cell_score[m * NCELLS + tid] * rinv;
    int idx = g_cell_idx[m * NCELLS + tid];
    bool valid = score > THRESH;
    float key = valid ? score : -1.0f;

    __shared__ float skey[256];
    skey[tid] = key;
    __syncthreads();

    int rank = 0;
    for (int j = 0; j < 256; j++) {
        float kj = skey[j];
        if (kj > key || (kj == key && j < tid)) rank++;   // stable descending
    }

    int cy = tid >> 4, cx = tid & 15;
    int ly = idx >> 6, lx = idx & 63;
    float x = valid ? (float)(cx * 64 + lx) : -1.0f;
    float y = valid ? (float)(cy * 64 + ly) : -1.0f;
    float s = valid ? score : -1.0f;
    float* po = out + m * (NCELLS * 3) + rank * 3;
    po[0] = x; po[1] = y; po[2] = s;

    // bg: global min over upsampled map; ties -> lowest flat index
    __shared__ float sv[256]; __shared__ int si[256];
    sv[tid] = g_cmin_val[m * NCELLS + tid];
    si[tid] = g_cmin_idx[m * NCELLS + tid];
    __syncthreads();
    if (tid == 0) {
        float mv = sv[0]; int mi = si[0];
        for (int t = 1; t < 256; t++) {
            if (sv[t] < mv || (sv[t] == mv && si[t] < mi)) { mv = sv[t]; mi = si[t]; }
        }
        float* pb = out + NMAPS * NCELLS * 3 + m * 2;
        pb[0] = (float)(mi & 1023);   // x = col
        pb[1] = (float)(mi >> 10);    // y = row
    }
}

// ---------------------------------------------------------------------------
extern "C" void kernel_launch(void* const* d_in, const int* in_sizes, int n_in,
                              void* d_out, int out_size) {
    const float* feat = (const float*)d_in[0];  // [1,256,64,64]
    const float* ref  = (const float*)d_in[1];  // [32,1,256]
    if (n_in >= 2 && in_sizes[0] == NMAPS * CDIM) {  // defensive: order by size
        ref  = (const float*)d_in[0];
        feat = (const float*)d_in[1];
    }
    (void)out_size;

    dim3 g1(128, NCHUNK);
    k_gemm<<<g1, 256>>>(feat, ref);
    dim3 g1b(16, NMAPS);
    k_combine<<<g1b, 256>>>();
    dim3 g2(NCELLS, NMAPS);
    k_cells<<<g2, 64>>>();
    k_sort<<<NMAPS, 256>>>((float*)d_out, ref);
}

// round 6
// speedup vs baseline: 2.0696x; 1.3265x over previous
#include <cuda_runtime.h>
#include <math.h>

#define NMAPS 32
#define CDIM 256
#define HW 4096          // 64*64
#define NCELLS 256       // 16*16 cells per map
#define NCHUNK 8         // split-K chunks (32 channels each)
#define THRESH 0.65f

// ---------------- device scratch (no allocations allowed) ----------------
__device__ float g_part[NCHUNK * NMAPS * HW];   // partial dots (ref un-normalized; deferred)
__device__ float g_ssp[NCHUNK * HW];            // partial per-pixel sum-of-squares
__device__ float g_cell_score[NMAPS * NCELLS];
__device__ int   g_cell_idx[NMAPS * NCELLS];    // ly*64+lx within cell
__device__ float g_cmin_val[NMAPS * NCELLS];
__device__ int   g_cmin_idx[NMAPS * NCELLS];    // gy*1024+gx flat index

// ---------------------------------------------------------------------------
// K1: split-K partial GEMM. grid = (128 pixel-tiles, 8 chunks), 256 threads.
// Thread = (pixel 0..31, ref-group 0..7 of 4 refs). 32 channels per block.
// ref tile transposed: the 4 ref weights come from ONE broadcast LDS.128.
// ---------------------------------------------------------------------------
__global__ void k_gemm(const float* __restrict__ feat, const float* __restrict__ ref) {
    __shared__ __align__(16) float sref_t[32][32];   // [channel][ref]
    int tid = threadIdx.x;
    int chunk = blockIdx.y;

    for (int i = tid; i < 32 * 32; i += 256) {
        int c = i >> 5, r = i & 31;
        sref_t[c][r] = ref[r * CDIM + chunk * 32 + c];
    }
    __syncthreads();

    int pix = blockIdx.x * 32 + (tid & 31);
    int rg  = tid >> 5;                 // warp-uniform
    const float* fp = feat + chunk * 32 * HW + pix;

    float a0 = 0.f, a1 = 0.f, a2 = 0.f, a3 = 0.f, ss = 0.f;
    #pragma unroll
    for (int c = 0; c < 32; c++) {
        float v = fp[c * HW];                                              // coalesced
        float4 r4 = *reinterpret_cast<const float4*>(&sref_t[c][rg * 4]);  // broadcast
        ss += v * v;
        a0 = fmaf(r4.x, v, a0);
        a1 = fmaf(r4.y, v, a1);
        a2 = fmaf(r4.z, v, a2);
        a3 = fmaf(r4.w, v, a3);
    }
    float* po = g_part + (chunk * NMAPS + rg * 4) * HW + pix;
    po[0] = a0; po[HW] = a1; po[2 * HW] = a2; po[3 * HW] = a3;
    if (rg == 0) g_ssp[chunk * HW + pix] = ss;
}

// ---------------------------------------------------------------------------
// K2: per (map, cell): fused combine + separable bilinear eval of the 64x64
// upsampled cell. Threads 0..35 gather the 6x6 source patch directly from the
// split-K partials (sum 8 chunks + per-pixel norm). Then thread = ox; x-interp
// once into sH[6][64]; y-loop runs as 5 constant-li segments with ty stepping
// by exactly 1/16 (bit-identical to table version) -> zero smem in inner loop.
// Tracks cell argmax (row-major first-occurrence) and global-flat argmin.
// ---------------------------------------------------------------------------
__global__ void k_cells() {
    int cell = blockIdx.x;
    int m = blockIdx.y;
    int cy = cell >> 4, cx = cell & 15;
    int tid = threadIdx.x;   // = ox

    __shared__ float patch[6][8];
    __shared__ float sH[6][64];
    __shared__ float rmaxv[2]; __shared__ int rmaxi[2];
    __shared__ float rminv[2]; __shared__ int rmini[2];

    if (tid < 36) {
        int i = tid / 6, j = tid - i * 6;
        int sr = min(max(4 * cy - 1 + i, 0), 63);
        int sc = min(max(4 * cx - 1 + j, 0), 63);
        int pix = sr * 64 + sc;
        float ss = 0.f, d = 0.f;
        #pragma unroll
        for (int c = 0; c < NCHUNK; c++) ss += g_ssp[c * HW + pix];
        #pragma unroll
        for (int c = 0; c < NCHUNK; c++) d += g_part[(c * NMAPS + m) * HW + pix];
        patch[i][j] = d * (1.0f / (sqrtf(ss) + 1e-12f));
    }
    __syncthreads();

    // x-interp column for this thread's ox
    {
        float fx = ((float)(cx * 64 + tid) - 7.5f) * 0.0625f;
        int jx = (int)floorf(fx);
        jx = min(max(jx, 0), 62);
        float tx = fminf(fmaxf(fx - (float)jx, 0.f), 1.f);
        int lj = jx - (4 * cx - 1);
        float wx0 = 1.0f - tx;
        #pragma unroll
        for (int i = 0; i < 6; i++)
            sH[i][tid] = wx0 * patch[i][lj] + tx * patch[i][lj + 1];
    }
    __syncthreads();

    float bestv = -1e30f; int bestoy = 0;
    float minv  =  1e30f; int minoy  = 0;
    int oy = 0;
    #pragma unroll
    for (int s = 0; s < 5; s++) {
        const int seg_len = (s == 0 || s == 4) ? 8 : 16;
        int jy_t = 4 * cy - 1 + s;
        int jy_c = min(max(jy_t, 0), 62);
        int li = jy_c - (4 * cy - 1);
        float ty, step;
        if (jy_t < 0)       { ty = 0.0f;                       step = 0.0f;     }
        else if (jy_t > 62) { ty = 1.0f;                       step = 0.0f;     }
        else                { ty = (s == 0) ? 0.53125f : 0.03125f; step = 0.0625f; }
        float r0 = sH[li][tid], r1 = sH[li + 1][tid];
        #pragma unroll
        for (int k = 0; k < seg_len; k++) {
            float v = (1.0f - ty) * r0 + ty * r1;
            if (v > bestv) { bestv = v; bestoy = oy; }   // smallest oy on ties
            if (v < minv)  { minv  = v; minoy  = oy; }
            ty += step; oy++;
        }
    }

    int bidx = bestoy * 64 + tid;                              // cell-local row-major
    int midx = ((cy * 64 + minoy) << 10) + cx * 64 + tid;      // global flat
    #pragma unroll
    for (int off = 16; off; off >>= 1) {
        float ov = __shfl_down_sync(0xFFFFFFFFu, bestv, off);
        int   oi = __shfl_down_sync(0xFFFFFFFFu, bidx, off);
        if (ov > bestv || (ov == bestv && oi < bidx)) { bestv = ov; bidx = oi; }
        float mv = __shfl_down_sync(0xFFFFFFFFu, minv, off);
        int   mi = __shfl_down_sync(0xFFFFFFFFu, midx, off);
        if (mv < minv || (mv == minv && mi < midx)) { minv = mv; midx = mi; }
    }
    int w = tid >> 5;
    if ((tid & 31) == 0) { rmaxv[w] = bestv; rmaxi[w] = bidx; rminv[w] = minv; rmini[w] = midx; }
    __syncthreads();
    if (tid == 0) {
        float bv = rmaxv[0]; int bi = rmaxi[0];
        if (rmaxv[1] > bv || (rmaxv[1] == bv && rmaxi[1] < bi)) { bv = rmaxv[1]; bi = rmaxi[1]; }
        float mv = rminv[0]; int mi = rmini[0];
        if (rminv[1] < mv || (rminv[1] == mv && rmini[1] < mi)) { mv = rminv[1]; mi = rmini[1]; }
        g_cell_score[m * NCELLS + cell] = bv;
        g_cell_idx[m * NCELLS + cell]   = bi;
        g_cmin_val[m * NCELLS + cell]   = mv;
        g_cmin_idx[m * NCELLS + cell]   = mi;
    }
}

// ---------------------------------------------------------------------------
// K3: per map: deferred ref-norm scale, threshold, stable descending rank sort
// (unique ranks -> collision-free scatter), bg via parallel tree min-reduce.
// grid = 32 maps, 256 threads. Output: points [32,256,3] then bg [32,1,2].
// ---------------------------------------------------------------------------
__global__ void k_sort(float* __restrict__ out, const float* __restrict__ ref) {
    int m = blockIdx.x;
    int tid = threadIdx.x;

    __shared__ __align__(16) float skey[256];           // 16B-aligned: read via LDS.128
    __shared__ __align__(16) float sv[256];
    __shared__ int si[256];
    __shared__ float red[8];
    __shared__ float s_rinv;

    // ref-norm reciprocal for this map (tree reduce)
    {
        float v = ref[m * CDIM + tid];
        float p = v * v;
        #pragma unroll
        for (int off = 16; off; off >>= 1) p += __shfl_down_sync(0xFFFFFFFFu, p, off);
        if ((tid & 31) == 0) red[tid >> 5] = p;
    }
    // start bg loads while reducing
    sv[tid] = g_cmin_val[m * NCELLS + tid];
    si[tid] = g_cmin_idx[m * NCELLS + tid];
    __syncthreads();
    if (tid == 0) {
        float s = 0.f;
        #pragma unroll
        for (int i = 0; i < 8; i++) s += red[i];
        s_rinv = 1.0f / (sqrtf(s) + 1e-12f);
    }
    __syncthreads();
    float rinv = s_rinv;

    float score = g_cell_score[m * NCELLS + tid] * rinv;
    int idx = g_cell_idx[m * NCELLS + tid];
    bool valid = score > THRESH;
    float key = valid ? score : -1.0f;
    skey[tid] = key;
    __syncthreads();

    // stable descending rank: count strictly-greater keys + equal keys earlier
    int rank = 0;
    const float4* sk4 = reinterpret_cast<const float4*>(skey);
    #pragma unroll 8
    for (int q = 0; q < 64; q++) {
        float4 kk = sk4[q];
        int j = q * 4;
        rank += (kk.x > key) || (kk.x == key && (j + 0) < tid);
        rank += (kk.y > key) || (kk.y == key && (j + 1) < tid);
        rank += (kk.z > key) || (kk.z == key && (j + 2) < tid);
        rank += (kk.w > key) || (kk.w == key && (j + 3) < tid);
    }

    int cy = tid >> 4, cx = tid & 15;
    int ly = idx >> 6, lx = idx & 63;
    float* po = out + m * (NCELLS * 3) + rank * 3;
    po[0] = valid ? (float)(cx * 64 + lx) : -1.0f;
    po[1] = valid ? (float)(cy * 64 + ly) : -1.0f;
    po[2] = valid ? score : -1.0f;

    // bg: parallel tree min-reduce (ties -> lowest flat index)
    #pragma unroll
    for (int s2 = 128; s2 >= 1; s2 >>= 1) {
        __syncthreads();
        if (tid < s2) {
            float ov = sv[tid + s2]; int oi = si[tid + s2];
            if (ov < sv[tid] || (ov == sv[tid] && oi < si[tid])) { sv[tid] = ov; si[tid] = oi; }
        }
    }
    if (tid == 0) {
        int mi = si[0];
        float* pb = out + NMAPS * NCELLS * 3 + m * 2;
        pb[0] = (float)(mi & 1023);   // x = col
        pb[1] = (float)(mi >> 10);    // y = row
    }
}

// ---------------------------------------------------------------------------
extern "C" void kernel_launch(void* const* d_in, const int* in_sizes, int n_in,
                              void* d_out, int out_size) {
    const float* feat = (const float*)d_in[0];  // [1,256,64,64]
    const float* ref  = (const float*)d_in[1];  // [32,1,256]
    if (n_in >= 2 && in_sizes[0] == NMAPS * CDIM) {  // defensive: order by size
        ref  = (const float*)d_in[0];
        feat = (const float*)d_in[1];
    }
    (void)out_size;

    dim3 g1(128, NCHUNK);
    k_gemm<<<g1, 256>>>(feat, ref);
    dim3 g2(NCELLS, NMAPS);
    k_cells<<<g2, 64>>>();
    k_sort<<<NMAPS, 256>>>((float*)d_out, ref);
}